// round 7
// baseline (speedup 1.0000x reference)
#include <cuda_runtime.h>
#include <math.h>

// HG2Vec fused loss, single persistent kernel, v7 = v6 + full rotating double buffer.
// Decomposition: warp per (position, context-pair), 5 warps/block = 1 position.
//  - 14 register accumulators (2 score + 12 info)
//  - 2-stage software pipeline with TWO 11-row register buffers (A/B rotation):
//    loads of stage k+1 always issue before FMAs of stage k, so no load->use
//    back-to-back remains (v6 still exposed 2 latencies/iter on chunks 1,2)
//  - roles alternate per iteration: loop body manually unrolled 2x (no reg copies)
//  - scattered 16-value warp reduction (31 shfl), fast softplus (MUFU)
//  - __launch_bounds__(160,3): <=136 regs, 3 CTAs/SM, grid 444 = one wave
//  - last-block-done deterministic reduction, counter self-resets (graph-safe)

#define DIM       300
#define ROWBYTES  1200u
#define NPOS      16384          // B*L
#define GRID      444            // 148 SMs * 3 resident CTAs
#define THREADS   160            // 5 warps = 1 position (2 contexts per warp)

__device__ float        g_partial[GRID];
__device__ unsigned int g_ticket = 0;

struct Rows {
    float4 t, a0, a1, b0, b1, f[6];
};

// load one d-chunk of all 11 rows of the current position into R
#define LOADR(R, JB)                                                        \
    do {                                                                    \
        (R).t  = *(const float4*)(Wout_b + puo  + (JB));                    \
        (R).a0 = *(const float4*)(Win_b  + pvo0 + (JB));                    \
        (R).a1 = *(const float4*)(Win_b  + pvo1 + (JB));                    \
        (R).b0 = *(const float4*)(Wout_b + pvo0 + (JB));                    \
        (R).b1 = *(const float4*)(Wout_b + pvo1 + (JB));                    \
        _Pragma("unroll")                                                   \
        for (int i_ = 0; i_ < 6; i_++)                                      \
            (R).f[i_] = *(const float4*)(Win_b + ivo[i_] + (JB));           \
    } while (0)

// accumulate one chunk from R into (sc0, sc1, ai[12])
#define FMAR(R)                                                             \
    do {                                                                    \
        sc0 += (R).a0.x * (R).t.x + (R).a0.y * (R).t.y                      \
             + (R).a0.z * (R).t.z + (R).a0.w * (R).t.w;                     \
        sc1 += (R).a1.x * (R).t.x + (R).a1.y * (R).t.y                      \
             + (R).a1.z * (R).t.z + (R).a1.w * (R).t.w;                     \
        _Pragma("unroll")                                                   \
        for (int i_ = 0; i_ < 6; i_++) {                                    \
            ai[i_]     += (R).b0.x * (R).f[i_].x + (R).b0.y * (R).f[i_].y   \
                        + (R).b0.z * (R).f[i_].z + (R).b0.w * (R).f[i_].w;  \
            ai[6 + i_] += (R).b1.x * (R).f[i_].x + (R).b1.y * (R).f[i_].y   \
                        + (R).b1.z * (R).f[i_].z + (R).b1.w * (R).f[i_].w;  \
        }                                                                   \
    } while (0)

// one pipelined iteration. Precondition: X holds chunk0 of position p.
// Postcondition: Y holds chunk0 of position p+GRID, offsets advanced, p += GRID.
#define ITER(X, Y)                                                          \
    do {                                                                    \
        const int pn = p + GRID;                                            \
        const int ps = (pn < NPOS) ? pn : 0;                                \
        const int n_pu  = pos_u[ps];                                        \
        const int n_pv0 = pos_v[ps * 10 + w * 2 + 0];                       \
        const int n_pv1 = pos_v[ps * 10 + w * 2 + 1];                       \
        int n_iv[6];                                                        \
        _Pragma("unroll")                                                   \
        for (int i_ = 0; i_ < 6; i_++) n_iv[i_] = info_v[ps * 6 + i_];      \
        float sc0 = 0.f, sc1 = 0.f;                                         \
        float ai[12];                                                       \
        _Pragma("unroll")                                                   \
        for (int q_ = 0; q_ < 12; q_++) ai[q_] = 0.f;                       \
        LOADR(Y, jb1);                 /* chunk1 in flight           */     \
        FMAR(X);                       /* chunk0 (preloaded)         */     \
        if (lane < 11) LOADR(X, jb2);  /* chunk2 in flight           */     \
        FMAR(Y);                       /* chunk1                     */     \
        puo  = (unsigned)n_pu  * ROWBYTES;                                  \
        pvo0 = (unsigned)n_pv0 * ROWBYTES;                                  \
        pvo1 = (unsigned)n_pv1 * ROWBYTES;                                  \
        _Pragma("unroll")                                                   \
        for (int i_ = 0; i_ < 6; i_++)                                      \
            ivo[i_] = (unsigned)n_iv[i_] * ROWBYTES;                        \
        LOADR(Y, jb0);                 /* next chunk0 in flight      */     \
        if (lane < 11) FMAR(X);        /* chunk2                     */     \
        acc_loss += reduce_eval(sc0, sc1, ai, lane, t_pre, t_sgn, t_wt);    \
        p = pn;                                                             \
    } while (0)

// scattered 16-value warp reduction (31 shfl) + in-place loss term.
// v[16] = {sc0, sc1, ai[0..11], 0, 0}; sum of value q lands on lanes {2q, 2q+1}.
__device__ __forceinline__ float reduce_eval(
    float sc0, float sc1, const float* ai, int lane,
    float t_pre, float t_sgn, float t_wt)
{
    float v0[8], v1[4], v2[2], v3;
    {
        float a, b;
        a = sc0   + __shfl_xor_sync(0xffffffffu, sc0,   16);
        b = ai[6] + __shfl_xor_sync(0xffffffffu, ai[6], 16);
        v0[0] = (lane & 16) ? b : a;
        a = sc1   + __shfl_xor_sync(0xffffffffu, sc1,   16);
        b = ai[7] + __shfl_xor_sync(0xffffffffu, ai[7], 16);
        v0[1] = (lane & 16) ? b : a;
#pragma unroll
        for (int q = 0; q < 4; q++) {
            a = ai[q]     + __shfl_xor_sync(0xffffffffu, ai[q],     16);
            b = ai[q + 8] + __shfl_xor_sync(0xffffffffu, ai[q + 8], 16);
            v0[2 + q] = (lane & 16) ? b : a;
        }
        a = ai[4] + __shfl_xor_sync(0xffffffffu, ai[4], 16);
        v0[6] = (lane & 16) ? 0.f : a;
        a = ai[5] + __shfl_xor_sync(0xffffffffu, ai[5], 16);
        v0[7] = (lane & 16) ? 0.f : a;
    }
#pragma unroll
    for (int q = 0; q < 4; q++) {
        const float a = v0[q]     + __shfl_xor_sync(0xffffffffu, v0[q],     8);
        const float b = v0[q + 4] + __shfl_xor_sync(0xffffffffu, v0[q + 4], 8);
        v1[q] = (lane & 8) ? b : a;
    }
#pragma unroll
    for (int q = 0; q < 2; q++) {
        const float a = v1[q]     + __shfl_xor_sync(0xffffffffu, v1[q],     4);
        const float b = v1[q + 2] + __shfl_xor_sync(0xffffffffu, v1[q + 2], 4);
        v2[q] = (lane & 4) ? b : a;
    }
    {
        const float a = v2[0] + __shfl_xor_sync(0xffffffffu, v2[0], 2);
        const float b = v2[1] + __shfl_xor_sync(0xffffffffu, v2[1], 2);
        v3 = (lane & 2) ? b : a;
    }
    v3 += __shfl_xor_sync(0xffffffffu, v3, 1);

    const float x = fminf(fmaxf(v3 * t_pre, -10.f), 10.f) * t_sgn;
    return __logf(1.f + __expf(-x)) * t_wt;
}

__global__ __launch_bounds__(THREADS, 3) void hg2vec_fused(
    const int*   __restrict__ pos_u,
    const int*   __restrict__ pos_v,
    const int*   __restrict__ info_v,
    const float* __restrict__ W_in,
    const float* __restrict__ W_out,
    const float* __restrict__ cmask,
    const float* __restrict__ sig_mask,
    const float* __restrict__ score_mask,
    float*       __restrict__ out)
{
    __shared__ float wloss[5];
    __shared__ bool  amLast;

    const int w    = threadIdx.x >> 5;     // 0..4 : context pair
    const int lane = threadIdx.x & 31;

    const char* __restrict__ Win_b  = (const char*)W_in;
    const char* __restrict__ Wout_b = (const char*)W_out;

    // ---- per-lane term coefficients; value index k = lane>>1 ----
    const int kk = lane >> 1;
    float t_pre = 1.f, t_sgn = 1.f, t_wt = 0.f;
    if (((lane & 1) == 0) && kk < 14) {
        if (kk < 2) { t_pre = cmask[w * 2 + kk]; t_sgn = 1.f; t_wt = 1.f; }
        else {
            const int i = (kk - 2) % 6;
            t_sgn = sig_mask[i];
            t_wt  = score_mask[i];
        }
    }

    const unsigned jb0 = (unsigned)lane * 16u;          // chunk0 byte offset
    const unsigned jb1 = jb0 + 512u;                    // chunk1
    const unsigned jb2 = jb0 + 1024u;                   // chunk2 (lanes 0..10)

    float acc_loss = 0.f;

    int p = blockIdx.x;

    // ---- prime: offsets for first p, chunk0 into buffer A ----
    unsigned puo  = (unsigned)pos_u[p] * ROWBYTES;
    unsigned pvo0 = (unsigned)pos_v[p * 10 + w * 2 + 0] * ROWBYTES;
    unsigned pvo1 = (unsigned)pos_v[p * 10 + w * 2 + 1] * ROWBYTES;
    unsigned ivo[6];
#pragma unroll
    for (int i = 0; i < 6; i++)
        ivo[i] = (unsigned)info_v[p * 6 + i] * ROWBYTES;

    Rows A, B;
    LOADR(A, jb0);

    // ---- main loop, 2x unrolled for A/B role rotation ----
    while (true) {
        ITER(A, B);                 // consumes chunk0 in A, leaves next chunk0 in B
        if (p >= NPOS) break;
        ITER(B, A);                 // consumes chunk0 in B, leaves next chunk0 in A
        if (p >= NPOS) break;
    }

    // ---- block reduction ----
#pragma unroll
    for (int off = 16; off; off >>= 1)
        acc_loss += __shfl_xor_sync(0xffffffffu, acc_loss, off);
    if (lane == 0) wloss[w] = acc_loss;
    __syncthreads();

    if (threadIdx.x == 0) {
        float s = wloss[0] + wloss[1] + wloss[2] + wloss[3] + wloss[4];
        g_partial[blockIdx.x] = s;
        __threadfence();
        unsigned t = atomicAdd(&g_ticket, 1u);
        amLast = (t == GRID - 1);
    }
    __syncthreads();

    // ---- last block: deterministic fixed-order final sum ----
    if (amLast) {
        __shared__ float fs[THREADS];
        float v = 0.f;
        for (int i = threadIdx.x; i < GRID; i += THREADS)
            v += __ldcg(&g_partial[i]);
        fs[threadIdx.x] = v;
        __syncthreads();
#pragma unroll
        for (int st = 128; st; st >>= 1) {
            if (threadIdx.x < st && threadIdx.x + st < THREADS)
                fs[threadIdx.x] += fs[threadIdx.x + st];
            __syncthreads();
        }
        if (threadIdx.x == 0) {
            out[0] = fs[0];
            g_ticket = 0;            // reset for next graph replay
            __threadfence();
        }
    }
}

extern "C" void kernel_launch(void* const* d_in, const int* in_sizes, int n_in,
                              void* d_out, int out_size)
{
    const int*   pos_u  = (const int*)  d_in[0];
    const int*   pos_v  = (const int*)  d_in[1];
    const int*   info_v = (const int*)  d_in[2];
    const float* W_in   = (const float*)d_in[3];
    const float* W_out  = (const float*)d_in[4];
    const float* cmask  = (const float*)d_in[5];
    const float* sigm   = (const float*)d_in[6];
    const float* smask  = (const float*)d_in[7];

    hg2vec_fused<<<GRID, THREADS>>>(pos_u, pos_v, info_v, W_in, W_out,
                                    cmask, sigm, smask, (float*)d_out);
}